// round 16
// baseline (speedup 1.0000x reference)
#include <cuda_runtime.h>
#include <cuda_fp16.h>
#include <math.h>
#include <stdint.h>

// Problem dims
#define DD    1024
#define EE    16
#define SS    16
#define ESL   256
#define BB    64
#define NT    256
#define BNR   16384
#define HH    256

// ---------------- scratch (device globals) -----------------------------------
__device__ __half g_xnh[(long long)BNR * DD];             // [B*N, D]
__device__ float  g_rnorm[BNR];
__device__ __half g_muuN[DD * ESL];                       // [d][es]
__device__ __half g_logitsh[(long long)BNR * ESL];
__device__ __half g_dispTh[(long long)BB * ESL * NT];     // [b][es][n]
__device__ __half g_combineh[(long long)BNR * ESL];       // [b][n][es]
__device__ __half g_slotinh[(long long)EE * 1024 * DD];   // [e][b*16+s][d]
__device__ __half g_hh[(long long)EE * 1024 * HH];        // [e][b*16+s][h]
__device__ __half g_slotouth[(long long)BB * ESL * DD];   // [b][es][d]
__device__ __half g_w1h[(long long)EE * DD * HH];
__device__ __half g_w2h[(long long)EE * HH * DD];

// ---------------- helpers -----------------------------------------------------
__device__ __forceinline__ uint32_t f2h2(float a, float b) {
    __half2 t = __floats2half2_rn(a, b);
    return *(uint32_t*)&t;
}
__device__ __forceinline__ void mma_f16(float* c, const uint32_t* a, const uint32_t* b) {
    asm volatile(
        "mma.sync.aligned.m16n8k16.row.col.f32.f16.f16.f32 "
        "{%0,%1,%2,%3}, {%4,%5,%6,%7}, {%8,%9}, {%0,%1,%2,%3};"
        : "+f"(c[0]), "+f"(c[1]), "+f"(c[2]), "+f"(c[3])
        : "r"(a[0]), "r"(a[1]), "r"(a[2]), "r"(a[3]), "r"(b[0]), "r"(b[1]));
}
__device__ __forceinline__ void ldsm_x4(uint32_t& r0, uint32_t& r1, uint32_t& r2,
                                        uint32_t& r3, uint32_t addr) {
    asm volatile("ldmatrix.sync.aligned.m8n8.x4.shared.b16 {%0,%1,%2,%3}, [%4];"
                 : "=r"(r0), "=r"(r1), "=r"(r2), "=r"(r3) : "r"(addr));
}
__device__ __forceinline__ void ldsm_x4_t(uint32_t& r0, uint32_t& r1, uint32_t& r2,
                                          uint32_t& r3, uint32_t addr) {
    asm volatile("ldmatrix.sync.aligned.m8n8.x4.trans.shared.b16 {%0,%1,%2,%3}, [%4];"
                 : "=r"(r0), "=r"(r1), "=r"(r2), "=r"(r3) : "r"(addr));
}
__device__ __forceinline__ void cpa16(uint32_t dst, const void* src) {
    asm volatile("cp.async.cg.shared.global [%0], [%1], 16;" :: "r"(dst), "l"(src));
}
#define CP_COMMIT() asm volatile("cp.async.commit_group;" ::: "memory")
#define CP_WAIT2()  asm volatile("cp.async.wait_group 2;" ::: "memory")
__device__ __forceinline__ float gelu_f(float v) {
    return 0.5f * v * (1.0f + erff(v * 0.70710678118654752f));
}
__device__ __forceinline__ float warpSum(float v) {
    #pragma unroll
    for (int o = 16; o > 0; o >>= 1) v += __shfl_xor_sync(0xffffffffu, v, o);
    return v;
}
__device__ __forceinline__ float warpMax(float v) {
    #pragma unroll
    for (int o = 16; o > 0; o >>= 1) v = fmaxf(v, __shfl_xor_sync(0xffffffffu, v, o));
    return v;
}
__device__ __forceinline__ float blockReduceSum256(float v, float* sh) {
    #pragma unroll
    for (int o = 16; o > 0; o >>= 1) v += __shfl_down_sync(0xffffffffu, v, o);
    int lane = threadIdx.x & 31, w = threadIdx.x >> 5;
    if (lane == 0) sh[w] = v;
    __syncthreads();
    if (w == 0) {
        float t = (lane < 8) ? sh[lane] : 0.0f;
        #pragma unroll
        for (int o = 4; o > 0; o >>= 1) t += __shfl_down_sync(0xffu, t, o);
        if (lane == 0) sh[0] = t;
    }
    __syncthreads();
    float r = sh[0];
    __syncthreads();
    return r;
}

// ---------------- f32 -> f16 bulk convert (both weight tensors) ---------------
#define WQUADS (EE * DD * HH / 4)
__global__ void f2h_both(const float* __restrict__ w1, __half* __restrict__ o1,
                         const float* __restrict__ w2, __half* __restrict__ o2) {
    int i = blockIdx.x * blockDim.x + threadIdx.x;
    const float* in = (i < WQUADS) ? w1 : w2;
    __half* out = (i < WQUADS) ? o1 : o2;
    int j = (i < WQUADS) ? i : i - WQUADS;
    float4 v = ((const float4*)in)[j];
    ((uint2*)out)[j] = make_uint2(f2h2(v.x, v.y), f2h2(v.z, v.w));
}

// ---------------- LayerNorm + row inv-norm (warp-per-row) ---------------------
__global__ void ln_warp(const float* __restrict__ x, const float* __restrict__ gamma,
                        const float* __restrict__ beta, const float* __restrict__ scale) {
    int w = threadIdx.x >> 5, lane = threadIdx.x & 31;
    int row = blockIdx.x * 8 + w;
    const float4* xr = (const float4*)(x + (long long)row * DD);
    float4 v[8];
    float s = 0.0f, sq = 0.0f;
    #pragma unroll
    for (int i = 0; i < 8; i++) {
        v[i] = xr[lane + (i << 5)];
        s  += v[i].x + v[i].y + v[i].z + v[i].w;
        sq += v[i].x*v[i].x + v[i].y*v[i].y + v[i].z*v[i].z + v[i].w*v[i].w;
    }
    s = warpSum(s); sq = warpSum(sq);
    float mean = s * (1.0f / DD);
    float var  = sq * (1.0f / DD) - mean * mean;
    float rstd = rsqrtf(var + 1e-5f);
    float nq = 0.0f;
    uint2* xo = (uint2*)(g_xnh + (long long)row * DD);
    #pragma unroll
    for (int i = 0; i < 8; i++) {
        float4 g  = ((const float4*)gamma)[lane + (i << 5)];
        float4 be = ((const float4*)beta)[lane + (i << 5)];
        float4 o;
        o.x = (v[i].x - mean) * rstd * g.x + be.x;
        o.y = (v[i].y - mean) * rstd * g.y + be.y;
        o.z = (v[i].z - mean) * rstd * g.z + be.z;
        o.w = (v[i].w - mean) * rstd * g.w + be.w;
        xo[lane + (i << 5)] = make_uint2(f2h2(o.x, o.y), f2h2(o.z, o.w));
        nq += o.x*o.x + o.y*o.y + o.z*o.z + o.w*o.w;
    }
    nq = warpSum(nq);
    if (lane == 0)
        g_rnorm[row] = scale[0] / fmaxf(sqrtf(nq), 1e-12f);
}

// ---------------- mu unit columns ([d][es], half) -----------------------------
__global__ void mu_kernel(const float* __restrict__ mu) {
    __shared__ float sh[8];
    int es = blockIdx.x;
    float vals[4];
    float sq = 0.0f;
    #pragma unroll
    for (int i = 0; i < 4; i++) {
        int d = threadIdx.x + i * 256;
        vals[i] = mu[(long long)d * ESL + es];
        sq += vals[i] * vals[i];
    }
    sq = blockReduceSum256(sq, sh);
    float inv = 1.0f / fmaxf(sqrtf(sq), 1e-12f);
    #pragma unroll
    for (int i = 0; i < 4; i++) {
        int d = threadIdx.x + i * 256;
        g_muuN[(long long)d * ESL + es] = __float2half_rn(vals[i] * inv);
    }
}

// ---------------- combine softmax (warp-per-row) ------------------------------
__global__ void softmax_combine_warp() {
    int w = threadIdx.x >> 5, lane = threadIdx.x & 31;
    long long row = blockIdx.x * 8 + w;
    const uint2* lr = (const uint2*)(g_logitsh + row * ESL);
    float4 v[2];
    float mx = -INFINITY;
    #pragma unroll
    for (int i = 0; i < 2; i++) {
        uint2 raw = lr[lane + (i << 5)];
        float2 f0 = __half22float2(*(__half2*)&raw.x);
        float2 f1 = __half22float2(*(__half2*)&raw.y);
        v[i] = make_float4(f0.x, f0.y, f1.x, f1.y);
        mx = fmaxf(mx, fmaxf(fmaxf(v[i].x, v[i].y), fmaxf(v[i].z, v[i].w)));
    }
    mx = warpMax(mx);
    float sm = 0.0f;
    #pragma unroll
    for (int i = 0; i < 2; i++) {
        v[i].x = __expf(v[i].x - mx); v[i].y = __expf(v[i].y - mx);
        v[i].z = __expf(v[i].z - mx); v[i].w = __expf(v[i].w - mx);
        sm += v[i].x + v[i].y + v[i].z + v[i].w;
    }
    sm = warpSum(sm);
    float inv = 1.0f / sm;
    uint2* cr = (uint2*)(g_combineh + row * ESL);
    #pragma unroll
    for (int i = 0; i < 2; i++)
        cr[lane + (i << 5)] = make_uint2(f2h2(v[i].x * inv, v[i].y * inv),
                                         f2h2(v[i].z * inv, v[i].w * inv));
}

// dispatch softmax over tokens n, via shared transpose. grid (8, 64)
__global__ void softmax_dispatch2() {
    __shared__ float T[32][257];
    int b = blockIdx.y, es0 = blockIdx.x * 32;
    int tid = threadIdx.x, wid = tid >> 5, lane = tid & 31;
    #pragma unroll 4
    for (int i = 0; i < 32; i++) {
        int n = (i << 3) + wid;
        T[lane][n] = __half2float(g_logitsh[((long long)(b * NT + n)) * ESL + es0 + lane]);
    }
    __syncthreads();
    #pragma unroll
    for (int r = 0; r < 4; r++) {
        int es_l = (wid << 2) + r;
        float mx = -INFINITY;
        #pragma unroll
        for (int k = 0; k < 8; k++) mx = fmaxf(mx, T[es_l][lane + (k << 5)]);
        mx = warpMax(mx);
        float sm = 0.0f;
        #pragma unroll
        for (int k = 0; k < 8; k++) sm += __expf(T[es_l][lane + (k << 5)] - mx);
        sm = warpSum(sm);
        float inv = 1.0f / sm;
        #pragma unroll
        for (int k = 0; k < 8; k++) {
            int n = lane + (k << 5);
            g_dispTh[((long long)b * ESL + es0 + es_l) * NT + n] =
                __float2half_rn(__expf(T[es_l][n] - mx) * inv);
        }
    }
}

// ---------------- fp16 mma GEMM: cp.async 4-stage (3 ahead), ldmatrix ---------
// C[128x128 tile] = A[M,K] * B[K,N], fp16, f32 accum.
// 256 thr = 8 warps (4m x 2n), warp tile 32x64.
// A smem: [128 rows][80B stride] -> conflict-free LDSM.  B: [32 k][256B] xor k&7.
// MODE 4: logits   MODE 1: slot_in   MODE 2: MLP1(gelu)  MODE 3: MLP2  MODE 0: out
#define A_STRIDE 80
#define A_BYTES  (128 * A_STRIDE)
#define B_BYTES  (32 * 256)
#define STAGE_BYTES (A_BYTES + B_BYTES)
#define NSTAGE 4
#define GEMM_SMEM (NSTAGE * STAGE_BYTES)

template <int MODE>
__global__ void __launch_bounds__(256, 2) gemm_mma(const float* __restrict__ bias,
                                                   float* __restrict__ Cout) {
    constexpr int KK = (MODE == 4 || MODE == 2) ? 1024 : 256;
    constexpr int NN = (MODE == 4 || MODE == 2) ? 256 : 1024;
    constexpr int NC = KK / 32;

    extern __shared__ __align__(16) char smem[];
    const uint32_t smb = (uint32_t)__cvta_generic_to_shared(smem);

    int tid = threadIdx.x, wid = tid >> 5, lane = tid & 31;
    int wm = wid >> 1, wn = wid & 1;
    int qq = lane >> 2, rr = lane & 3;
    int z = blockIdx.z;
    int row0 = blockIdx.y * 128, col0 = blockIdx.x * 128;

    const __half* A;
    const __half* B;
    if (MODE == 4)      { A = g_xnh;                                B = g_muuN; }
    else if (MODE == 1) { A = g_dispTh   + (long long)z * ESL * NT; B = g_xnh       + (long long)z * NT * DD; }
    else if (MODE == 2) { A = g_slotinh  + (long long)z * 1024 * DD;B = g_w1h       + (long long)z * DD * HH; }
    else if (MODE == 3) { A = g_hh       + (long long)z * 1024 * HH;B = g_w2h       + (long long)z * HH * DD; }
    else                { A = g_combineh + (long long)z * NT * ESL; B = g_slotouth  + (long long)z * ESL * DD; }

    // loader coords: A -> row ar, 16B-chunks ac, ac+1; B -> k-row bk, chunks bc, bc+1
    const int ar = tid >> 1, ac = (tid & 1) << 1;
    const int bk = tid >> 3, bc = (tid & 7) << 1;
    const __half* ApA = A + (long long)(row0 + ar) * KK + (ac << 3);
    const __half* BpB = B + (long long)bk * NN + col0 + (bc << 3);
    const uint32_t aDst = smb + ar * A_STRIDE + ac * 16;
    const uint32_t bDst0 = smb + A_BYTES + bk * 256 + ((bc ^ (bk & 7)) << 4);
    const uint32_t bDst1 = smb + A_BYTES + bk * 256 + (((bc + 1) ^ (bk & 7)) << 4);

    // LDSM lane mapping (per warp)
    const int a_row = wm * 32 + ((lane >> 3) & 1) * 8 + (lane & 7);
    const int a_ch  = lane >> 4;
    const int b_k   = ((lane >> 3) & 1) * 8 + (lane & 7);
    const int b_ch  = lane >> 4;

    float acc[2][8][4];
    #pragma unroll
    for (int i = 0; i < 2; i++)
        #pragma unroll
        for (int j = 0; j < 8; j++)
            #pragma unroll
            for (int c = 0; c < 4; c++) acc[i][j][c] = 0.0f;

    // prologue: issue stages 0..2 (3 chunks ahead)
    #pragma unroll
    for (int s = 0; s < 3; s++) {
        int ko = s << 5;
        uint32_t sb = s * STAGE_BYTES;
        cpa16(aDst + sb,      ApA + ko);
        cpa16(aDst + sb + 16, ApA + ko + 8);
        cpa16(bDst0 + sb, BpB + (long long)ko * NN);
        cpa16(bDst1 + sb, BpB + (long long)ko * NN + 8);
        CP_COMMIT();
    }

    int stage = 0;
    for (int kc = 0; kc < NC; kc++) {
        CP_WAIT2();
        __syncthreads();

        // issue chunk kc+3 into the freed buffer (all warps past compute(kc-1))
        if (kc + 3 < NC) {
            int ko = (kc + 3) << 5;
            uint32_t sb = ((stage + 3) & 3) * STAGE_BYTES;
            cpa16(aDst + sb,      ApA + ko);
            cpa16(aDst + sb + 16, ApA + ko + 8);
            cpa16(bDst0 + sb, BpB + (long long)ko * NN);
            cpa16(bDst1 + sb, BpB + (long long)ko * NN + 8);
        }
        CP_COMMIT();

        // compute on stage buffer
        const uint32_t sA = smb + stage * STAGE_BYTES;
        const uint32_t sB = sA + A_BYTES;
        #pragma unroll
        for (int ks = 0; ks < 2; ks++) {
            uint32_t af[2][4], bf[8][2];
            #pragma unroll
            for (int mt = 0; mt < 2; mt++) {
                uint32_t addr = sA + (a_row + mt * 16) * A_STRIDE + ((ks << 1) + a_ch) * 16;
                ldsm_x4(af[mt][0], af[mt][1], af[mt][2], af[mt][3], addr);
            }
            #pragma unroll
            for (int ntp = 0; ntp < 4; ntp++) {
                int k = (ks << 4) + b_k;
                int c = (wn << 3) + (ntp << 1) + b_ch;
                uint32_t addr = sB + k * 256 + ((c ^ (k & 7)) << 4);
                ldsm_x4_t(bf[2 * ntp][0], bf[2 * ntp][1],
                          bf[2 * ntp + 1][0], bf[2 * ntp + 1][1], addr);
            }
            #pragma unroll
            for (int mt = 0; mt < 2; mt++)
                #pragma unroll
                for (int nt = 0; nt < 8; nt++)
                    mma_f16(acc[mt][nt], af[mt], bf[nt]);
        }
        stage = (stage + 1) & 3;
    }

    // ---------------- epilogue ----------------
    #pragma unroll
    for (int mt = 0; mt < 2; mt++) {
        int rbase = row0 + wm * 32 + mt * 16 + qq;
        #pragma unroll
        for (int h = 0; h < 2; h++) {
            int m = rbase + h * 8;
            float rn = (MODE == 4) ? g_rnorm[m] : 1.0f;
            #pragma unroll
            for (int nt = 0; nt < 8; nt++) {
                int col = col0 + wn * 64 + nt * 8 + (rr << 1);
                float ox = acc[mt][nt][h * 2], oy = acc[mt][nt][h * 2 + 1];
                if (MODE == 4) {
                    *(uint32_t*)(g_logitsh + (long long)m * ESL + col) = f2h2(ox * rn, oy * rn);
                } else if (MODE == 1) {
                    int e = m >> 4, s = m & 15;
                    *(uint32_t*)(g_slotinh + ((long long)(e * BB + z) * SS + s) * DD + col) = f2h2(ox, oy);
                } else if (MODE == 2) {
                    float2 bb = *(const float2*)(bias + (long long)z * HH + col);
                    *(uint32_t*)(g_hh + ((long long)z * 1024 + m) * HH + col) =
                        f2h2(gelu_f(ox + bb.x), gelu_f(oy + bb.y));
                } else if (MODE == 3) {
                    float2 bb = *(const float2*)(bias + (long long)z * DD + col);
                    int b = m >> 4, s = m & 15;
                    *(uint32_t*)(g_slotouth + ((long long)b * ESL + z * SS + s) * DD + col) =
                        f2h2(ox + bb.x, oy + bb.y);
                } else {
                    *(float2*)(Cout + ((long long)z * NT + m) * DD + col) = make_float2(ox, oy);
                }
            }
        }
    }
}

// ---------------- launch ------------------------------------------------------
extern "C" void kernel_launch(void* const* d_in, const int* in_sizes, int n_in,
                              void* d_out, int out_size) {
    const float* x     = (const float*)d_in[0];
    const float* gamma = (const float*)d_in[1];
    const float* beta  = (const float*)d_in[2];
    const float* mu    = (const float*)d_in[3];
    const float* scale = (const float*)d_in[4];
    const float* w1    = (const float*)d_in[5];
    const float* b1    = (const float*)d_in[6];
    const float* w2    = (const float*)d_in[7];
    const float* b2    = (const float*)d_in[8];
    float* out = (float*)d_out;
    (void)in_sizes; (void)n_in; (void)out_size;

    void *p_w1h, *p_w2h;
    cudaGetSymbolAddress(&p_w1h, g_w1h);
    cudaGetSymbolAddress(&p_w2h, g_w2h);

    cudaFuncSetAttribute(gemm_mma<4>, cudaFuncAttributeMaxDynamicSharedMemorySize, GEMM_SMEM);
    cudaFuncSetAttribute(gemm_mma<1>, cudaFuncAttributeMaxDynamicSharedMemorySize, GEMM_SMEM);
    cudaFuncSetAttribute(gemm_mma<2>, cudaFuncAttributeMaxDynamicSharedMemorySize, GEMM_SMEM);
    cudaFuncSetAttribute(gemm_mma<3>, cudaFuncAttributeMaxDynamicSharedMemorySize, GEMM_SMEM);
    cudaFuncSetAttribute(gemm_mma<0>, cudaFuncAttributeMaxDynamicSharedMemorySize, GEMM_SMEM);

    ln_warp<<<BNR / 8, 256>>>(x, gamma, beta, scale);
    mu_kernel<<<ESL, 256>>>(mu);
    f2h_both<<<(2 * WQUADS) / 256, 256>>>(w1, (__half*)p_w1h, w2, (__half*)p_w2h);
    // logits: M=16384, N=256, K=1024
    gemm_mma<4><<<dim3(2, 128, 1), 256, GEMM_SMEM>>>(nullptr, nullptr);
    softmax_combine_warp<<<BNR / 8, 256>>>();
    softmax_dispatch2<<<dim3(8, BB), 256>>>();
    // slot_in: per b, M=256(es), N=1024(d), K=256(n)
    gemm_mma<1><<<dim3(8, 2, BB), 256, GEMM_SMEM>>>(nullptr, nullptr);
    // MLP1: per e, M=1024(b*s), N=256(h), K=1024(d)
    gemm_mma<2><<<dim3(2, 8, EE), 256, GEMM_SMEM>>>(b1, nullptr);
    // MLP2: per e, M=1024(b*s), N=1024(d), K=256(h)
    gemm_mma<3><<<dim3(8, 8, EE), 256, GEMM_SMEM>>>(b2, nullptr);
    // out: per b, M=256(n), N=1024(d), K=256(es)
    gemm_mma<0><<<dim3(8, 2, BB), 256, GEMM_SMEM>>>(nullptr, out);
}

// round 17
// speedup vs baseline: 1.5184x; 1.5184x over previous
#include <cuda_runtime.h>
#include <cuda_fp16.h>
#include <math.h>
#include <stdint.h>

// Problem dims
#define DD    1024
#define EE    16
#define SS    16
#define ESL   256
#define BB    64
#define NT    256
#define BNR   16384
#define HH    256

// ---------------- scratch (device globals) -----------------------------------
__device__ __half g_xnh[(long long)BNR * DD];             // [B*N, D]
__device__ float  g_rnorm[BNR];
__device__ __half g_muuN[DD * ESL];                       // [d][es]
__device__ __half g_logitsh[(long long)BNR * ESL];
__device__ __half g_dispTh[(long long)BB * ESL * NT];     // [b][es][n]
__device__ __half g_combineh[(long long)BNR * ESL];       // [b][n][es]
__device__ __half g_slotinh[(long long)EE * 1024 * DD];   // [e][b*16+s][d]
__device__ __half g_hh[(long long)EE * 1024 * HH];        // [e][b*16+s][h]
__device__ __half g_slotouth[(long long)BB * ESL * DD];   // [b][es][d]
__device__ __half g_w1h[(long long)EE * DD * HH];
__device__ __half g_w2h[(long long)EE * HH * DD];

// ---------------- helpers -----------------------------------------------------
__device__ __forceinline__ uint32_t f2h2(float a, float b) {
    __half2 t = __floats2half2_rn(a, b);
    return *(uint32_t*)&t;
}
__device__ __forceinline__ void mma_f16(float* c, const uint32_t* a, const uint32_t* b) {
    asm volatile(
        "mma.sync.aligned.m16n8k16.row.col.f32.f16.f16.f32 "
        "{%0,%1,%2,%3}, {%4,%5,%6,%7}, {%8,%9}, {%0,%1,%2,%3};"
        : "+f"(c[0]), "+f"(c[1]), "+f"(c[2]), "+f"(c[3])
        : "r"(a[0]), "r"(a[1]), "r"(a[2]), "r"(a[3]), "r"(b[0]), "r"(b[1]));
}
__device__ __forceinline__ void ldsm_x4(uint32_t& r0, uint32_t& r1, uint32_t& r2,
                                        uint32_t& r3, uint32_t addr) {
    asm volatile("ldmatrix.sync.aligned.m8n8.x4.shared.b16 {%0,%1,%2,%3}, [%4];"
                 : "=r"(r0), "=r"(r1), "=r"(r2), "=r"(r3) : "r"(addr));
}
__device__ __forceinline__ void ldsm_x4_t(uint32_t& r0, uint32_t& r1, uint32_t& r2,
                                          uint32_t& r3, uint32_t addr) {
    asm volatile("ldmatrix.sync.aligned.m8n8.x4.trans.shared.b16 {%0,%1,%2,%3}, [%4];"
                 : "=r"(r0), "=r"(r1), "=r"(r2), "=r"(r3) : "r"(addr));
}
__device__ __forceinline__ void cpa16(uint32_t dst, const void* src) {
    asm volatile("cp.async.cg.shared.global [%0], [%1], 16;" :: "r"(dst), "l"(src));
}
#define CP_COMMIT() asm volatile("cp.async.commit_group;" ::: "memory")
#define CP_WAIT1()  asm volatile("cp.async.wait_group 1;" ::: "memory")
__device__ __forceinline__ float gelu_f(float v) {
    return 0.5f * v * (1.0f + erff(v * 0.70710678118654752f));
}
__device__ __forceinline__ float warpSum(float v) {
    #pragma unroll
    for (int o = 16; o > 0; o >>= 1) v += __shfl_xor_sync(0xffffffffu, v, o);
    return v;
}
__device__ __forceinline__ float warpMax(float v) {
    #pragma unroll
    for (int o = 16; o > 0; o >>= 1) v = fmaxf(v, __shfl_xor_sync(0xffffffffu, v, o));
    return v;
}

// ---------------- fat_pre: ln (blocks 0..2047) + mu (2048..2303) --------------
#define LN_BLOCKS   (BNR / 8)          // 2048
#define MU_BLOCKS   ESL                 // 256
#define PRE_BLOCKS  (LN_BLOCKS + MU_BLOCKS)

__global__ void fat_pre(const float* __restrict__ x, const float* __restrict__ gamma,
                        const float* __restrict__ beta, const float* __restrict__ scale,
                        const float* __restrict__ mu) {
    if (blockIdx.x < LN_BLOCKS) {
        // -------- LayerNorm + row inv-norm (warp-per-row) --------
        int w = threadIdx.x >> 5, lane = threadIdx.x & 31;
        int row = blockIdx.x * 8 + w;
        const float4* xr = (const float4*)(x + (long long)row * DD);
        float4 v[8];
        float s = 0.0f, sq = 0.0f;
        #pragma unroll
        for (int i = 0; i < 8; i++) {
            v[i] = xr[lane + (i << 5)];
            s  += v[i].x + v[i].y + v[i].z + v[i].w;
            sq += v[i].x*v[i].x + v[i].y*v[i].y + v[i].z*v[i].z + v[i].w*v[i].w;
        }
        s = warpSum(s); sq = warpSum(sq);
        float mean = s * (1.0f / DD);
        float var  = sq * (1.0f / DD) - mean * mean;
        float rstd = rsqrtf(var + 1e-5f);
        float nq = 0.0f;
        uint2* xo = (uint2*)(g_xnh + (long long)row * DD);
        #pragma unroll
        for (int i = 0; i < 8; i++) {
            float4 g  = ((const float4*)gamma)[lane + (i << 5)];
            float4 be = ((const float4*)beta)[lane + (i << 5)];
            float4 o;
            o.x = (v[i].x - mean) * rstd * g.x + be.x;
            o.y = (v[i].y - mean) * rstd * g.y + be.y;
            o.z = (v[i].z - mean) * rstd * g.z + be.z;
            o.w = (v[i].w - mean) * rstd * g.w + be.w;
            xo[lane + (i << 5)] = make_uint2(f2h2(o.x, o.y), f2h2(o.z, o.w));
            nq += o.x*o.x + o.y*o.y + o.z*o.z + o.w*o.w;
        }
        nq = warpSum(nq);
        if (lane == 0)
            g_rnorm[row] = scale[0] / fmaxf(sqrtf(nq), 1e-12f);
    } else {
        // -------- mu unit columns: one block per es, warp-split over d -------
        int es = blockIdx.x - LN_BLOCKS;
        float vals[4];
        float sq = 0.0f;
        #pragma unroll
        for (int i = 0; i < 4; i++) {
            int d = threadIdx.x + i * 256;
            vals[i] = mu[(long long)d * ESL + es];
            sq += vals[i] * vals[i];
        }
        // block reduce via shared
        __shared__ float sh[8];
        #pragma unroll
        for (int o = 16; o > 0; o >>= 1) sq += __shfl_down_sync(0xffffffffu, sq, o);
        int lane = threadIdx.x & 31, w = threadIdx.x >> 5;
        if (lane == 0) sh[w] = sq;
        __syncthreads();
        float tot;
        {
            float t = (lane < 8) ? sh[lane] : 0.0f;
            #pragma unroll
            for (int o = 4; o > 0; o >>= 1) t += __shfl_down_sync(0xffu, t, o);
            if (w == 0 && lane == 0) sh[0] = t;
        }
        __syncthreads();
        tot = sh[0];
        float inv = 1.0f / fmaxf(sqrtf(tot), 1e-12f);
        #pragma unroll
        for (int i = 0; i < 4; i++) {
            int d = threadIdx.x + i * 256;
            g_muuN[(long long)d * ESL + es] = __float2half_rn(vals[i] * inv);
        }
    }
}

// ------ fat_soft: combine (0..2047) + dispatch (2048..2559) + f2h (2560..) ----
#define CB_BLOCKS   (BNR / 8)                   // 2048
#define DP_BLOCKS   (8 * BB)                    // 512
#define WQUADS      (EE * DD * HH / 4)          // 1048576
#define F2H_BLOCKS  ((2 * WQUADS) / 256)        // 8192
#define SOFT_BLOCKS (CB_BLOCKS + DP_BLOCKS + F2H_BLOCKS)

__global__ void fat_soft(const float* __restrict__ w1, __half* __restrict__ o1,
                         const float* __restrict__ w2, __half* __restrict__ o2) {
    if (blockIdx.x < CB_BLOCKS) {
        // -------- combine softmax (warp-per-row over es) --------
        int w = threadIdx.x >> 5, lane = threadIdx.x & 31;
        long long row = blockIdx.x * 8 + w;
        const uint2* lr = (const uint2*)(g_logitsh + row * ESL);
        float4 v[2];
        float mx = -INFINITY;
        #pragma unroll
        for (int i = 0; i < 2; i++) {
            uint2 raw = lr[lane + (i << 5)];
            float2 f0 = __half22float2(*(__half2*)&raw.x);
            float2 f1 = __half22float2(*(__half2*)&raw.y);
            v[i] = make_float4(f0.x, f0.y, f1.x, f1.y);
            mx = fmaxf(mx, fmaxf(fmaxf(v[i].x, v[i].y), fmaxf(v[i].z, v[i].w)));
        }
        mx = warpMax(mx);
        float sm = 0.0f;
        #pragma unroll
        for (int i = 0; i < 2; i++) {
            v[i].x = __expf(v[i].x - mx); v[i].y = __expf(v[i].y - mx);
            v[i].z = __expf(v[i].z - mx); v[i].w = __expf(v[i].w - mx);
            sm += v[i].x + v[i].y + v[i].z + v[i].w;
        }
        sm = warpSum(sm);
        float inv = 1.0f / sm;
        uint2* cr = (uint2*)(g_combineh + row * ESL);
        #pragma unroll
        for (int i = 0; i < 2; i++)
            cr[lane + (i << 5)] = make_uint2(f2h2(v[i].x * inv, v[i].y * inv),
                                             f2h2(v[i].z * inv, v[i].w * inv));
    } else if (blockIdx.x < CB_BLOCKS + DP_BLOCKS) {
        // -------- dispatch softmax (over tokens n) via shared transpose ------
        __shared__ float T[32][257];
        int bx = blockIdx.x - CB_BLOCKS;
        int b = bx >> 3, es0 = (bx & 7) * 32;
        int tid = threadIdx.x, wid = tid >> 5, lane = tid & 31;
        #pragma unroll 4
        for (int i = 0; i < 32; i++) {
            int n = (i << 3) + wid;
            T[lane][n] = __half2float(g_logitsh[((long long)(b * NT + n)) * ESL + es0 + lane]);
        }
        __syncthreads();
        #pragma unroll
        for (int r = 0; r < 4; r++) {
            int es_l = (wid << 2) + r;
            float mx = -INFINITY;
            #pragma unroll
            for (int k = 0; k < 8; k++) mx = fmaxf(mx, T[es_l][lane + (k << 5)]);
            mx = warpMax(mx);
            float sm = 0.0f;
            #pragma unroll
            for (int k = 0; k < 8; k++) sm += __expf(T[es_l][lane + (k << 5)] - mx);
            sm = warpSum(sm);
            float inv = 1.0f / sm;
            #pragma unroll
            for (int k = 0; k < 8; k++) {
                int n = lane + (k << 5);
                g_dispTh[((long long)b * ESL + es0 + es_l) * NT + n] =
                    __float2half_rn(__expf(T[es_l][n] - mx) * inv);
            }
        }
    } else {
        // -------- f32 -> f16 weight convert --------
        int i = (blockIdx.x - CB_BLOCKS - DP_BLOCKS) * 256 + threadIdx.x;
        const float* in = (i < WQUADS) ? w1 : w2;
        __half* out = (i < WQUADS) ? o1 : o2;
        int j = (i < WQUADS) ? i : i - WQUADS;
        float4 v = ((const float4*)in)[j];
        ((uint2*)out)[j] = make_uint2(f2h2(v.x, v.y), f2h2(v.z, v.w));
    }
}

// ---------------- fp16 mma GEMM: cp.async 3-stage, ldmatrix (R13 config) ------
// C[128x128 tile] = A[M,K] * B[K,N], fp16, f32 accum.
// 256 thr = 8 warps (4m x 2n), warp tile 32x64.
// A smem: [128 rows][80B stride] -> conflict-free LDSM.  B: [32 k][256B] xor k&7.
// MODE 4: logits   MODE 1: slot_in   MODE 2: MLP1(gelu)  MODE 3: MLP2  MODE 0: out
#define A_STRIDE 80
#define A_BYTES  (128 * A_STRIDE)
#define B_BYTES  (32 * 256)
#define STAGE_BYTES (A_BYTES + B_BYTES)
#define NSTAGE 3
#define GEMM_SMEM (NSTAGE * STAGE_BYTES)

template <int MODE>
__global__ void __launch_bounds__(256, 2) gemm_mma(const float* __restrict__ bias,
                                                   float* __restrict__ Cout) {
    constexpr int KK = (MODE == 4 || MODE == 2) ? 1024 : 256;
    constexpr int NN = (MODE == 4 || MODE == 2) ? 256 : 1024;
    constexpr int NC = KK / 32;

    extern __shared__ __align__(16) char smem[];
    const uint32_t smb = (uint32_t)__cvta_generic_to_shared(smem);

    int tid = threadIdx.x, wid = tid >> 5, lane = tid & 31;
    int wm = wid >> 1, wn = wid & 1;
    int qq = lane >> 2, rr = lane & 3;
    int z = blockIdx.z;
    int row0 = blockIdx.y * 128, col0 = blockIdx.x * 128;

    const __half* A;
    const __half* B;
    if (MODE == 4)      { A = g_xnh;                                B = g_muuN; }
    else if (MODE == 1) { A = g_dispTh   + (long long)z * ESL * NT; B = g_xnh       + (long long)z * NT * DD; }
    else if (MODE == 2) { A = g_slotinh  + (long long)z * 1024 * DD;B = g_w1h       + (long long)z * DD * HH; }
    else if (MODE == 3) { A = g_hh       + (long long)z * 1024 * HH;B = g_w2h       + (long long)z * HH * DD; }
    else                { A = g_combineh + (long long)z * NT * ESL; B = g_slotouth  + (long long)z * ESL * DD; }

    // loader coords: A -> row ar, 16B-chunks ac, ac+1; B -> k-row bk, chunks bc, bc+1
    const int ar = tid >> 1, ac = (tid & 1) << 1;
    const int bk = tid >> 3, bc = (tid & 7) << 1;
    const __half* ApA = A + (long long)(row0 + ar) * KK + (ac << 3);
    const __half* BpB = B + (long long)bk * NN + col0 + (bc << 3);
    const uint32_t aDst = smb + ar * A_STRIDE + ac * 16;
    const uint32_t bDst0 = smb + A_BYTES + bk * 256 + ((bc ^ (bk & 7)) << 4);
    const uint32_t bDst1 = smb + A_BYTES + bk * 256 + (((bc + 1) ^ (bk & 7)) << 4);

    // LDSM lane mapping (per warp)
    const int a_row = wm * 32 + ((lane >> 3) & 1) * 8 + (lane & 7);
    const int a_ch  = lane >> 4;
    const int b_k   = ((lane >> 3) & 1) * 8 + (lane & 7);
    const int b_ch  = lane >> 4;

    float acc[2][8][4];
    #pragma unroll
    for (int i = 0; i < 2; i++)
        #pragma unroll
        for (int j = 0; j < 8; j++)
            #pragma unroll
            for (int c = 0; c < 4; c++) acc[i][j][c] = 0.0f;

    // prologue: issue stages 0 and 1
    #pragma unroll
    for (int s = 0; s < 2; s++) {
        int ko = s << 5;
        uint32_t sb = s * STAGE_BYTES;
        cpa16(aDst + sb,      ApA + ko);
        cpa16(aDst + sb + 16, ApA + ko + 8);
        cpa16(bDst0 + sb, BpB + (long long)ko * NN);
        cpa16(bDst1 + sb, BpB + (long long)ko * NN + 8);
        CP_COMMIT();
    }

    int stage = 0;
    for (int kc = 0; kc < NC; kc++) {
        CP_WAIT1();
        __syncthreads();

        // issue chunk kc+2 into the freed buffer (all warps past compute(kc-1))
        if (kc + 2 < NC) {
            int ko = (kc + 2) << 5;
            int ns = stage + 2; if (ns >= NSTAGE) ns -= NSTAGE;
            uint32_t sb = ns * STAGE_BYTES;
            cpa16(aDst + sb,      ApA + ko);
            cpa16(aDst + sb + 16, ApA + ko + 8);
            cpa16(bDst0 + sb, BpB + (long long)ko * NN);
            cpa16(bDst1 + sb, BpB + (long long)ko * NN + 8);
        }
        CP_COMMIT();

        // compute on stage buffer
        const uint32_t sA = smb + stage * STAGE_BYTES;
        const uint32_t sB = sA + A_BYTES;
        #pragma unroll
        for (int ks = 0; ks < 2; ks++) {
            uint32_t af[2][4], bf[8][2];
            #pragma unroll
            for (int mt = 0; mt < 2; mt++) {
                uint32_t addr = sA + (a_row + mt * 16) * A_STRIDE + ((ks << 1) + a_ch) * 16;
                ldsm_x4(af[mt][0], af[mt][1], af[mt][2], af[mt][3], addr);
            }
            #pragma unroll
            for (int ntp = 0; ntp < 4; ntp++) {
                int k = (ks << 4) + b_k;
                int c = (wn << 3) + (ntp << 1) + b_ch;
                uint32_t addr = sB + k * 256 + ((c ^ (k & 7)) << 4);
                ldsm_x4_t(bf[2 * ntp][0], bf[2 * ntp][1],
                          bf[2 * ntp + 1][0], bf[2 * ntp + 1][1], addr);
            }
            #pragma unroll
            for (int mt = 0; mt < 2; mt++)
                #pragma unroll
                for (int nt = 0; nt < 8; nt++)
                    mma_f16(acc[mt][nt], af[mt], bf[nt]);
        }
        stage = stage + 1; if (stage >= NSTAGE) stage = 0;
    }

    // ---------------- epilogue ----------------
    #pragma unroll
    for (int mt = 0; mt < 2; mt++) {
        int rbase = row0 + wm * 32 + mt * 16 + qq;
        #pragma unroll
        for (int h = 0; h < 2; h++) {
            int m = rbase + h * 8;
            float rn = (MODE == 4) ? g_rnorm[m] : 1.0f;
            #pragma unroll
            for (int nt = 0; nt < 8; nt++) {
                int col = col0 + wn * 64 + nt * 8 + (rr << 1);
                float ox = acc[mt][nt][h * 2], oy = acc[mt][nt][h * 2 + 1];
                if (MODE == 4) {
                    *(uint32_t*)(g_logitsh + (long long)m * ESL + col) = f2h2(ox * rn, oy * rn);
                } else if (MODE == 1) {
                    int e = m >> 4, s = m & 15;
                    *(uint32_t*)(g_slotinh + ((long long)(e * BB + z) * SS + s) * DD + col) = f2h2(ox, oy);
                } else if (MODE == 2) {
                    float2 bb = *(const float2*)(bias + (long long)z * HH + col);
                    *(uint32_t*)(g_hh + ((long long)z * 1024 + m) * HH + col) =
                        f2h2(gelu_f(ox + bb.x), gelu_f(oy + bb.y));
                } else if (MODE == 3) {
                    float2 bb = *(const float2*)(bias + (long long)z * DD + col);
                    int b = m >> 4, s = m & 15;
                    *(uint32_t*)(g_slotouth + ((long long)b * ESL + z * SS + s) * DD + col) =
                        f2h2(ox + bb.x, oy + bb.y);
                } else {
                    *(float2*)(Cout + ((long long)z * NT + m) * DD + col) = make_float2(ox, oy);
                }
            }
        }
    }
}

// ---------------- launch ------------------------------------------------------
extern "C" void kernel_launch(void* const* d_in, const int* in_sizes, int n_in,
                              void* d_out, int out_size) {
    const float* x     = (const float*)d_in[0];
    const float* gamma = (const float*)d_in[1];
    const float* beta  = (const float*)d_in[2];
    const float* mu    = (const float*)d_in[3];
    const float* scale = (const float*)d_in[4];
    const float* w1    = (const float*)d_in[5];
    const float* b1    = (const float*)d_in[6];
    const float* w2    = (const float*)d_in[7];
    const float* b2    = (const float*)d_in[8];
    float* out = (float*)d_out;
    (void)in_sizes; (void)n_in; (void)out_size;

    void *p_w1h, *p_w2h;
    cudaGetSymbolAddress(&p_w1h, g_w1h);
    cudaGetSymbolAddress(&p_w2h, g_w2h);

    cudaFuncSetAttribute(gemm_mma<4>, cudaFuncAttributeMaxDynamicSharedMemorySize, GEMM_SMEM);
    cudaFuncSetAttribute(gemm_mma<1>, cudaFuncAttributeMaxDynamicSharedMemorySize, GEMM_SMEM);
    cudaFuncSetAttribute(gemm_mma<2>, cudaFuncAttributeMaxDynamicSharedMemorySize, GEMM_SMEM);
    cudaFuncSetAttribute(gemm_mma<3>, cudaFuncAttributeMaxDynamicSharedMemorySize, GEMM_SMEM);
    cudaFuncSetAttribute(gemm_mma<0>, cudaFuncAttributeMaxDynamicSharedMemorySize, GEMM_SMEM);

    // ln + mu (concurrent, independent)
    fat_pre<<<PRE_BLOCKS, 256>>>(x, gamma, beta, scale, mu);
    // logits: M=16384, N=256, K=1024
    gemm_mma<4><<<dim3(2, 128, 1), 256, GEMM_SMEM>>>(nullptr, nullptr);
    // combine + dispatch softmaxes + w1/w2 fp16 convert (concurrent)
    fat_soft<<<SOFT_BLOCKS, 256>>>(w1, (__half*)p_w1h, w2, (__half*)p_w2h);
    // slot_in: per b, M=256(es), N=1024(d), K=256(n)
    gemm_mma<1><<<dim3(8, 2, BB), 256, GEMM_SMEM>>>(nullptr, nullptr);
    // MLP1: per e, M=1024(b*s), N=256(h), K=1024(d)
    gemm_mma<2><<<dim3(2, 8, EE), 256, GEMM_SMEM>>>(b1, nullptr);
    // MLP2: per e, M=1024(b*s), N=1024(d), K=256(h)
    gemm_mma<3><<<dim3(8, 8, EE), 256, GEMM_SMEM>>>(b2, nullptr);
    // out: per b, M=256(n), N=1024(d), K=256(es)
    gemm_mma<0><<<dim3(8, 2, BB), 256, GEMM_SMEM>>>(nullptr, out);
}